// round 15
// baseline (speedup 1.0000x reference)
#include <cuda_runtime.h>
#include <cuda_fp16.h>
#include <math.h>
#include <stdint.h>

#define BB   2
#define SS   2048
#define DD   2048
#define HH   16
#define HKVN 4
#define HDN  128
#define MROWS (BB*SS)
#define NQKV 3072            // Q(2048) | K(512) | V(512)
#define CAP  (SS+32)

// ---------------- scratch ----------------------------------------------------
__device__ float  g_qkv[MROWS*NQKV];     // fused projections (fp32, standard layout)
__device__ float  g_bias[BB*HKVN*SS];
__device__ float  g_vmean[BB*HKVN*HDN];
__device__ float  g_vpart[8*8*HDN];
__device__ __half g_oh[MROWS*DD];        // attention out, fp16, NATURAL k order
__device__ __half g_xh[MROWS*DD];        // fp16 X, NATURAL k order
__device__ __half g_wbTh[NQKV*DD];       // [Wq|Wk|Wv]^T K-major, natural, fp16
__device__ __half g_woTh[DD*DD];         // Wo^T K-major, natural, fp16
__device__ float  g_wqg[DD*HKVN];
__device__ float  g_wvd[DD*HKVN];
__device__ __half g_ckh[BB*HKVN*CAP*HDN];  // compacted K, fp16, d pair-permuted
__device__ float  g_cv[BB*HKVN*CAP*HDN];   // compacted V, fp32 (vtrans input)
__device__ __half g_cvth[BB*HKVN*HDN*CAP]; // V^T [bn][d][key], fp16, key-permuted
__device__ float  g_cb[BB*HKVN*CAP];
__device__ int    g_cidx[BB*HKVN*CAP];
__device__ int    g_prefix[BB*HKVN*(SS+1)];

__device__ __forceinline__ void mma_fp16(float* c, const uint32_t* a, const uint32_t* b) {
    asm volatile(
        "mma.sync.aligned.m16n8k16.row.col.f32.f16.f16.f32 "
        "{%0,%1,%2,%3},{%4,%5,%6,%7},{%8,%9},{%0,%1,%2,%3};"
        : "+f"(c[0]), "+f"(c[1]), "+f"(c[2]), "+f"(c[3])
        : "r"(a[0]), "r"(a[1]), "r"(a[2]), "r"(a[3]), "r"(b[0]), "r"(b[1]));
}
__device__ __forceinline__ void ldsm_x4(uint32_t* r, uint32_t addr) {
    asm volatile("ldmatrix.sync.aligned.m8n8.x4.shared.b16 {%0,%1,%2,%3}, [%4];"
        : "=r"(r[0]), "=r"(r[1]), "=r"(r[2]), "=r"(r[3]) : "r"(addr));
}
#define CP16(dst, src) asm volatile("cp.async.cg.shared.global [%0], [%1], 16;" :: "r"(dst), "l"(src))

// pair-permutation of 32-bit words within 8-word groups (attention internal)
__device__ __forceinline__ int kperm8(int j) { return (j < 4) ? 2 * j : 2 * j - 7; }
__device__ __forceinline__ int kph(int j) {
    return (j & 16) | (kperm8((j >> 1) & 7) << 1) | (j & 1);
}

// ---------------- transpose + fp16 (natural): wbTh from Wq|Wk|Wv ------------
__global__ void transpose_wb(const float* __restrict__ Wq, const float* __restrict__ Wk,
                             const float* __restrict__ Wv) {
    __shared__ float t[32][33];
    int n0 = blockIdx.x * 32, k0 = blockIdx.y * 32;
    int tx = threadIdx.x & 31, ty = threadIdx.x >> 5;
    const float* src; int sN, scol;
    if (n0 < 2048)      { src = Wq; sN = 2048; scol = n0; }
    else if (n0 < 2560) { src = Wk; sN = 512;  scol = n0 - 2048; }
    else                { src = Wv; sN = 512;  scol = n0 - 2560; }
    #pragma unroll
    for (int i = 0; i < 32; i += 8)
        t[ty + i][tx] = src[(size_t)(k0 + ty + i) * sN + scol + tx];
    __syncthreads();
    #pragma unroll
    for (int i = 0; i < 32; i += 8)
        g_wbTh[(size_t)(n0 + ty + i) * DD + k0 + tx] = __float2half_rn(t[tx][ty + i]);
}

__global__ void transpose_wo(const float* __restrict__ Wo) {
    __shared__ float t[32][33];
    int n0 = blockIdx.x * 32, k0 = blockIdx.y * 32;
    int tx = threadIdx.x & 31, ty = threadIdx.x >> 5;
    #pragma unroll
    for (int i = 0; i < 32; i += 8)
        t[ty + i][tx] = Wo[(size_t)(k0 + ty + i) * DD + n0 + tx];
    __syncthreads();
    #pragma unroll
    for (int i = 0; i < 32; i += 8)
        g_woTh[(size_t)(n0 + ty + i) * DD + k0 + tx] = __float2half_rn(t[tx][ty + i]);
}

// ---------------- fused small weights ----------------------------------------
__global__ void fuse_both(const float* __restrict__ Wq, const float* __restrict__ Wg,
                          const float* __restrict__ Wv, const float* __restrict__ Wd) {
    int half_ = gridDim.x >> 1;
    const float* A; const float* B; float* out; int K;
    int blk = blockIdx.x;
    if (blk < half_) { A = Wq; B = Wg; out = g_wqg; K = DD; }
    else             { A = Wv; B = Wd; out = g_wvd; K = HKVN * HDN; blk -= half_; }
    int d    = (blk * blockDim.x + threadIdx.x) >> 5;
    int lane = threadIdx.x & 31;
    if (d >= DD) return;
    float a0 = 0.f, a1 = 0.f, a2 = 0.f, a3 = 0.f;
    const float* ar = A + (size_t)d * K;
    for (int j = lane; j < K; j += 32) {
        float a = ar[j];
        float4 b = *(const float4*)&B[j * 4];
        a0 += a * b.x; a1 += a * b.y; a2 += a * b.z; a3 += a * b.w;
    }
    #pragma unroll
    for (int off = 16; off; off >>= 1) {
        a0 += __shfl_xor_sync(0xffffffffu, a0, off);
        a1 += __shfl_xor_sync(0xffffffffu, a1, off);
        a2 += __shfl_xor_sync(0xffffffffu, a2, off);
        a3 += __shfl_xor_sync(0xffffffffu, a3, off);
    }
    if (lane == 0) { *(float4*)&out[d * 4] = make_float4(a0, a1, a2, a3); }
}

// ---------------- prep X v2: smem-cached weights, 16 rows/block -------------
// Per-row math byte-identical to prior prep_x (same thread mapping, same
// reduction order) -> bias bits unchanged. Weight L2 traffic 256MB -> 16MB.
#define PXROWS 16
#define PX_SMEM (2*DD*4*4)   // 65536 bytes (wqg + wvd as fp32)

__global__ void prep_x2(const float* __restrict__ X) {
    extern __shared__ float ws[];
    float* swg = ws;            // [DD*4]
    float* swd = ws + DD * 4;   // [DD*4]
    __shared__ float red[8][8];
    const int tid = threadIdx.x;
    const int lane = tid & 31, w = tid >> 5;

    for (int i = tid; i < DD; i += 256) {
        ((float4*)swg)[i] = *(const float4*)&g_wqg[i * 4];
        ((float4*)swd)[i] = *(const float4*)&g_wvd[i * 4];
    }
    __syncthreads();

    for (int rr = 0; rr < PXROWS; rr++) {
        const int row = blockIdx.x * PXROWS + rr;
        const float* xrow = X + (size_t)row * DD;
        float4 v0 = *(const float4*)(xrow + tid * 8);
        float4 v1 = *(const float4*)(xrow + tid * 8 + 4);
        float xs[8] = {v0.x, v0.y, v0.z, v0.w, v1.x, v1.y, v1.z, v1.w};
        float sg[4] = {0,0,0,0}, sd[4] = {0,0,0,0};
        #pragma unroll
        for (int j = 0; j < 8; j++) {
            int d = tid * 8 + j;
            float4 wg = *(const float4*)&swg[d * 4];
            float4 wv = *(const float4*)&swd[d * 4];
            sg[0] += xs[j]*wg.x; sg[1] += xs[j]*wg.y; sg[2] += xs[j]*wg.z; sg[3] += xs[j]*wg.w;
            sd[0] += xs[j]*wv.x; sd[1] += xs[j]*wv.y; sd[2] += xs[j]*wv.z; sd[3] += xs[j]*wv.w;
        }
        {   // natural fp16 store, one 16B write
            __half2 h[4];
            #pragma unroll
            for (int i = 0; i < 4; i++) h[i] = __floats2half2_rn(xs[2 * i], xs[2 * i + 1]);
            *(uint4*)&g_xh[(size_t)row * DD + tid * 8] = *(uint4*)h;
        }
        #pragma unroll
        for (int off = 16; off; off >>= 1)
            #pragma unroll
            for (int n = 0; n < 4; n++) {
                sg[n] += __shfl_xor_sync(0xffffffffu, sg[n], off);
                sd[n] += __shfl_xor_sync(0xffffffffu, sd[n], off);
            }
        if (lane == 0) {
            red[w][0] = sg[0]; red[w][1] = sg[1]; red[w][2] = sg[2]; red[w][3] = sg[3];
            red[w][4] = sd[0]; red[w][5] = sd[1]; red[w][6] = sd[2]; red[w][7] = sd[3];
        }
        __syncthreads();
        if (tid < 8) {
            float a = 0.f;
            #pragma unroll
            for (int ww = 0; ww < 8; ww++) a += red[ww][tid];
            red[0][tid] = a;
        }
        __syncthreads();
        if (tid < 4) {
            int b = row / SS, s = row % SS;
            g_bias[(b * HKVN + tid) * SS + s] = red[0][tid + 4] / (1.f + expf(-red[0][tid]));
        }
        __syncthreads();
    }
}

// ---------------- fp16 GEMM with ldmatrix fragment loads --------------------
#define BKH 64
#define STAGE_H (128*BKH)
#define NSTAGE 3
#define GEMM_SMEM (NSTAGE*2*STAGE_H*2)

__global__ __launch_bounds__(256, 2) void gemm_fp16(const __half* __restrict__ A,
                                                    const __half* __restrict__ B,
                                                    float* __restrict__ C,
                                                    int M, int N, int K) {
    extern __shared__ __half smh[];
    __half* As = smh;
    __half* Bs = smh + NSTAGE * STAGE_H;

    const int tid  = threadIdx.x;
    const int wid  = tid >> 5;
    const int lane = tid & 31;
    const int wm   = (wid & 3) << 5;
    const int wn   = (wid >> 2) << 6;
    const int m0   = blockIdx.y << 7;
    const int n0   = blockIdx.x << 7;
    const int lr   = lane >> 2;
    const int lc   = lane & 3;

    const int aRow0 = wm + (lane & 15);
    const int aCS   = lane >> 4;
    const int bRowB = wn + (((lane >> 4) & 1) << 3) + (lane & 7);
    const int bCS   = (lane >> 3) & 1;

    float acc[2][8][4];
    #pragma unroll
    for (int mt = 0; mt < 2; mt++)
        #pragma unroll
        for (int nt = 0; nt < 8; nt++)
            #pragma unroll
            for (int i = 0; i < 4; i++) acc[mt][nt][i] = 0.f;

    const int KT = K >> 6;

    auto load_stage = [&](int kt, int s) {
        __half* as = As + s * STAGE_H;
        __half* bs = Bs + s * STAGE_H;
        #pragma unroll
        for (int p = 0; p < 4; p++) {
            int idx = tid + (p << 8);
            int r = idx >> 3, c = idx & 7;
            uint32_t slot = (uint32_t)(c ^ (r & 7));
            CP16((uint32_t)__cvta_generic_to_shared(as + r * BKH + slot * 8),
                 A + (size_t)(m0 + r) * K + (kt << 6) + c * 8);
        }
        #pragma unroll
        for (int p = 0; p < 4; p++) {
            int idx = tid + (p << 8);
            int r = idx >> 3, c = idx & 7;
            uint32_t slot = (uint32_t)(c ^ (r & 7));
            CP16((uint32_t)__cvta_generic_to_shared(bs + r * BKH + slot * 8),
                 B + (size_t)(n0 + r) * K + (kt << 6) + c * 8);
        }
        asm volatile("cp.async.commit_group;");
    };

    load_stage(0, 0);
    if (KT > 1) load_stage(1, 1);

    int sc_ = 0;
    int sl_ = 2 % NSTAGE;

    for (int kt = 0; kt < KT; kt++) {
        if (kt + 2 < KT) { asm volatile("cp.async.wait_group 1;"); }
        else             { asm volatile("cp.async.wait_group 0;"); }
        __syncthreads();
        if (kt + 2 < KT) {
            load_stage(kt + 2, sl_);
            sl_ = (sl_ + 1 == NSTAGE) ? 0 : sl_ + 1;
        }

        uint32_t asb = (uint32_t)__cvta_generic_to_shared(As + sc_ * STAGE_H);
        uint32_t bsb = (uint32_t)__cvta_generic_to_shared(Bs + sc_ * STAGE_H);
        sc_ = (sc_ + 1 == NSTAGE) ? 0 : sc_ + 1;

        #pragma unroll
        for (int ks = 0; ks < 4; ks++) {
            uint32_t afr[2][4];
            #pragma unroll
            for (int mt = 0; mt < 2; mt++) {
                int row = aRow0 + (mt << 4);
                uint32_t addr = asb + row * 128 + ((((ks << 1) + aCS) ^ (row & 7)) << 4);
                ldsm_x4(afr[mt], addr);
            }
            #pragma unroll
            for (int ntp = 0; ntp < 4; ntp++) {
                int row = bRowB + (ntp << 4);
                uint32_t addr = bsb + row * 128 + ((((ks << 1) + bCS) ^ (row & 7)) << 4);
                uint32_t b4[4];
                ldsm_x4(b4, addr);
                mma_fp16(acc[0][2 * ntp],     afr[0], b4);
                mma_fp16(acc[1][2 * ntp],     afr[1], b4);
                mma_fp16(acc[0][2 * ntp + 1], afr[0], b4 + 2);
                mma_fp16(acc[1][2 * ntp + 1], afr[1], b4 + 2);
            }
        }
    }

    #pragma unroll
    for (int mt = 0; mt < 2; mt++) {
        #pragma unroll
        for (int nt = 0; nt < 8; nt++) {
            int row = m0 + wm + (mt << 4) + lr;
            int col = n0 + wn + (nt << 3) + (lc << 1);
            *(float2*)&C[(size_t)row * N + col] =
                make_float2(acc[mt][nt][0], acc[mt][nt][1]);
            *(float2*)&C[(size_t)(row + 8) * N + col] =
                make_float2(acc[mt][nt][2], acc[mt][nt][3]);
        }
    }
}

// ---------------- vmean (two-phase) ------------------------------------------
__global__ void vmean_part() {
    int ch = blockIdx.x, bn = blockIdx.y, d = threadIdx.x;
    int b = bn >> 2, n = bn & 3;
    float s = 0.f;
    int r0 = ch * 256;
    #pragma unroll 4
    for (int t = 0; t < 256; t++)
        s += g_qkv[(size_t)(b * SS + r0 + t) * NQKV + 2560 + n * HDN + d];
    g_vpart[(bn * 8 + ch) * HDN + d] = s;
}
__global__ void vmean_fin() {
    int bn = blockIdx.x, d = threadIdx.x;
    float s = 0.f;
    #pragma unroll
    for (int ch = 0; ch < 8; ch++) s += g_vpart[(bn * 8 + ch) * HDN + d];
    g_vmean[bn * HDN + d] = s * (1.f / SS);
}

// ---------------- compaction -------------------------------------------------
__global__ void scan_kernel() {
    __shared__ int wsum[32];
    int bn = blockIdx.x, t = threadIdx.x;
    int lane = t & 31, w = t >> 5;
    const float* bias = g_bias + bn * SS;
    int f0 = bias[2 * t]     > 0.f;
    int f1 = bias[2 * t + 1] > 0.f;
    int v = f0 + f1;
    int s = v;
    #pragma unroll
    for (int off = 1; off < 32; off <<= 1) {
        int u = __shfl_up_sync(0xffffffffu, s, off);
        if (lane >= off) s += u;
    }
    if (lane == 31) wsum[w] = s;
    __syncthreads();
    if (w == 0) {
        int ws = wsum[lane];
        #pragma unroll
        for (int off = 1; off < 32; off <<= 1) {
            int u = __shfl_up_sync(0xffffffffu, ws, off);
            if (lane >= off) ws += u;
        }
        wsum[lane] = ws;
    }
    __syncthreads();
    int base = (w > 0 ? wsum[w - 1] : 0) + s - v;
    int* pf = g_prefix + bn * (SS + 1);
    if (t == 0) pf[0] = 0;
    pf[2 * t + 1] = base + f0;
    pf[2 * t + 2] = base + f0 + f1;
}

__global__ void gather_kernel() {
    int bn = blockIdx.y;
    int b = bn >> 2, n = bn & 3;
    int w = threadIdx.x >> 5, lane = threadIdx.x & 31;
    int key = blockIdx.x * 8 + w;
    float bk = g_bias[bn * SS + key];
    if (bk > 0.f) {
        int pos = g_prefix[bn * (SS + 1) + key];
        size_t src = (size_t)(b * SS + key) * NQKV + 2048 + n * HDN + lane * 4;
        float4 kv = *(const float4*)(g_qkv + src);
        float4 vv = *(const float4*)(g_qkv + src + 512);
        int w0 = 2 * lane, w1 = w0 + 1;
        int p0 = (w0 & 56) | kperm8(w0 & 7);
        int p1 = (w1 & 56) | kperm8(w1 & 7);
        __half* kdst = g_ckh + ((size_t)bn * CAP + pos) * HDN;
        *(__half2*)(kdst + p0 * 2) = __floats2half2_rn(kv.x, kv.y);
        *(__half2*)(kdst + p1 * 2) = __floats2half2_rn(kv.z, kv.w);
        *(float4*)(g_cv + ((size_t)bn * CAP + pos) * HDN + lane * 4) = vv;
        if (lane == 0) { g_cb[bn * CAP + pos] = bk; g_cidx[bn * CAP + pos] = key; }
    }
}

__global__ void pad_kernel() {
    int bn = blockIdx.x;
    int nc = g_prefix[bn * (SS + 1) + SS];
    int r = threadIdx.x >> 5, lane = threadIdx.x & 31;
    int pos = nc + r;
    __half* kdst = g_ckh + ((size_t)bn * CAP + pos) * HDN + lane * 4;
    *(__half2*)(kdst)     = __floats2half2_rn(0.f, 0.f);
    *(__half2*)(kdst + 2) = __floats2half2_rn(0.f, 0.f);
    *(float4*)(g_cv + ((size_t)bn * CAP + pos) * HDN + lane * 4) = make_float4(0.f,0.f,0.f,0.f);
    if (lane == 0) { g_cidx[bn * CAP + pos] = 0x7fffffff; g_cb[bn * CAP + pos] = 0.f; }
}

// ---------------- vtrans: V^T [bn][d][key] fp16, key pair-permuted ----------
__global__ void vtrans_kernel() {
    __shared__ float t[32][33];
    int k0 = blockIdx.x * 32, d0 = blockIdx.y * 32, bn = blockIdx.z;
    int tx = threadIdx.x & 31, ty = threadIdx.x >> 5;
    #pragma unroll
    for (int i = 0; i < 32; i += 8)
        t[ty + i][tx] = g_cv[((size_t)bn * CAP + k0 + ty + i) * HDN + d0 + tx];
    __syncthreads();
    int kp = kph(tx);
    #pragma unroll
    for (int i = 0; i < 32; i += 8)
        g_cvth[((size_t)bn * HDN + d0 + ty + i) * CAP + k0 + kp] =
            __float2half_rn(t[tx][ty + i]);
}

// ---------------- fp16 tensor-core flash attention ---------------------------
#define QB   128
#define KB   32
#define Q_SH   (256*64)
#define K_SH   (64*64)
#define VT_SH  (128*48)
#define P_SH   (16*48)
#define ATTN_SMEM ((Q_SH + 2*K_SH + 2*VT_SH + 8*P_SH)*2 + 512)

__global__ __launch_bounds__(256) void attn_mma() {
    extern __shared__ __half sha[];
    __half* q_sh  = sha;
    __half* k_sh  = q_sh + Q_SH;
    __half* vt_sh = k_sh + 2 * K_SH;
    __half* p_sh  = vt_sh + 2 * VT_SH;
    float*  cb_sh = (float*)(p_sh + 8 * P_SH);
    int*    idx_sh = (int*)(cb_sh + 64);

    const int qblk = (gridDim.x - 1) - blockIdx.x;
    const int h    = blockIdx.y;
    const int b    = blockIdx.z;
    const int n    = h >> 2;
    const int bn   = b * HKVN + n;
    const int q0   = qblk * QB;
    const int tid  = threadIdx.x;
    const int w    = tid >> 5;
    const int lane = tid & 31;
    const int lr   = lane >> 2;
    const int lc   = lane & 3;
    const float scale = 0.08838834764831843f;

    {
        int qrow = tid >> 1;
        int sub  = tid & 1;
        int rr   = (qrow << 1) | sub;
        const float* src = g_qkv + (size_t)(b * SS + q0 + qrow) * NQKV + h * HDN + (sub << 6);
        __half* dst = q_sh + rr * 64;
        int xw = (rr & 3) << 3;
        #pragma unroll
        for (int j = 0; j < 16; j++) {
            float4 v = *(const float4*)(src + j * 4);
            int w0 = 2 * j, w1 = w0 + 1;
            int pp0 = (((w0 & 24) | kperm8(w0 & 7)) ^ xw);
            int pp1 = (((w1 & 24) | kperm8(w1 & 7)) ^ xw);
            *(__half2*)(dst + pp0 * 2) = __floats2half2_rn(v.x * scale, v.y * scale);
            *(__half2*)(dst + pp1 * 2) = __floats2half2_rn(v.z * scale, v.w * scale);
        }
    }

    const int limit  = g_prefix[bn * (SS + 1) + q0 + QB];
    const int ntiles = (limit + KB - 1) / KB;

    auto load_tile = [&](int kt, int st) {
        __half* ks = k_sh + st * K_SH;
        __half* vs = vt_sh + st * VT_SH;
        const __half* kg = g_ckh + ((size_t)bn * CAP + kt * KB) * HDN;
        #pragma unroll
        for (int p = 0; p < 2; p++) {
            int id = tid + (p << 8);
            int r = id >> 3, c = id & 7;
            uint32_t slot = (uint32_t)((2 * c) ^ ((r & 3) << 2));
            CP16((uint32_t)__cvta_generic_to_shared(ks + r * 64 + slot * 4),
                 kg + (size_t)(r >> 1) * HDN + ((r & 1) << 6) + c * 8);
        }
        #pragma unroll
        for (int p = 0; p < 2; p++) {
            int id = tid + (p << 8);
            int r = id >> 2, c = id & 3;
            CP16((uint32_t)__cvta_generic_to_shared(vs + r * 48 + c * 8),
                 g_cvth + ((size_t)bn * HDN + r) * CAP + kt * KB + c * 8);
        }
        if (tid < 8)
            CP16((uint32_t)__cvta_generic_to_shared(cb_sh + st * 32 + tid * 4),
                 g_cb + bn * CAP + kt * KB + tid * 4);
        else if (tid < 16)
            CP16((uint32_t)__cvta_generic_to_shared(idx_sh + st * 32 + (tid - 8) * 4),
                 g_cidx + bn * CAP + kt * KB + (tid - 8) * 4);
        asm volatile("cp.async.commit_group;");
    };

    float m0 = -INFINITY, m1 = -INFINITY, l0 = 0.f, l1 = 0.f;
    float oacc[16][4];
    #pragma unroll
    for (int nt = 0; nt < 16; nt++)
        #pragma unroll
        for (int i = 0; i < 4; i++) oacc[nt][i] = 0.f;

    const int qA = q0 + w * 16 + lr;
    __half* pw = p_sh + w * P_SH;

    if (ntiles > 0) load_tile(0, 0);

    for (int kt = 0; kt < ntiles; kt++) {
        const int st = kt & 1;
        asm volatile("cp.async.wait_group 0;");
        __syncthreads();
        if (kt + 1 < ntiles) load_tile(kt + 1, st ^ 1);

        const __half* ks = k_sh + st * K_SH;
        const __half* vs = vt_sh + st * VT_SH;
        const float*  cb = cb_sh + st * 32;
        const int*    ix = idx_sh + st * 32;

        float sc[4][4];
        #pragma unroll
        for (int nt = 0; nt < 4; nt++)
            #pragma unroll
            for (int i = 0; i < 4; i++) sc[nt][i] = 0.f;

        #pragma unroll
        for (int kc = 0; kc < 8; kc++) {
            const int dhi = kc >> 2, ksx = kc & 3;
            const int t3 = (2 * lr + dhi) & 3;
            const int fo = (4 * (ksx ^ t3) + lc) * 4;
            const int rr0 = (w << 5) + 2 * lr + dhi;
            uint2 f0 = *(const uint2*)(q_sh + rr0 * 64 + fo);
            uint2 f1 = *(const uint2*)(q_sh + (rr0 + 16) * 64 + fo);
            uint32_t a[4] = { f0.x, f1.x, f0.y, f1.y };
            #pragma unroll
            for (int nt = 0; nt < 4; nt++) {
                int kr = (nt << 4) + 2 * lr + dhi;
                uint2 g = *(const uint2*)(ks + kr * 64 + fo);
                uint32_t bb[2] = { g.x, g.y };
                mma_fp16(sc[nt], a, bb);
            }
        }

        #pragma unroll
        for (int nt = 0; nt < 4; nt++) {
            int c0 = nt * 8 + 2 * lc, c1 = c0 + 1;
            float bk0 = cb[c0], bk1 = cb[c1];
            int   i0  = ix[c0], i1  = ix[c1];
            sc[nt][0] = (i0 <= qA)     ? sc[nt][0] + bk0 : -INFINITY;
            sc[nt][1] = (i1 <= qA)     ? sc[nt][1] + bk1 : -INFINITY;
            sc[nt][2] = (i0 <= qA + 8) ? sc[nt][2] + bk0 : -INFINITY;
            sc[nt][3] = (i1 <= qA + 8) ? sc[nt][3] + bk1 : -INFINITY;
        }

        float tm0 = -INFINITY, tm1 = -INFINITY;
        #pragma unroll
        for (int nt = 0; nt < 4; nt++) {
            tm0 = fmaxf(tm0, fmaxf(sc[nt][0], sc[nt][1]));
            tm1 = fmaxf(tm1, fmaxf(sc[nt][2], sc[nt][3]));
        }
        tm0 = fmaxf(tm0, __shfl_xor_sync(0xffffffffu, tm0, 1));
        tm0 = fmaxf(tm0, __shfl_xor_sync(0xffffffffu, tm0, 2));
        tm1 = fmaxf(tm1, __shfl_xor_sync(0xffffffffu, tm1, 1));
        tm1 = fmaxf(tm1, __shfl_xor_sync(0xffffffffu, tm1, 2));
        float mn0 = fmaxf(m0, tm0), mn1 = fmaxf(m1, tm1);
        bool act0 = (mn0 > -INFINITY), act1 = (mn1 > -INFINITY);

        float rs0 = 0.f, rs1 = 0.f;
        #pragma unroll
        for (int nt = 0; nt < 4; nt++) {
            sc[nt][0] = act0 ? __expf(sc[nt][0] - mn0) : 0.f;
            sc[nt][1] = act0 ? __expf(sc[nt][1] - mn0) : 0.f;
            sc[nt][2] = act1 ? __expf(sc[nt][2] - mn1) : 0.f;
            sc[nt][3] = act1 ? __expf(sc[nt][3] - mn1) : 0.f;
            rs0 += sc[nt][0] + sc[nt][1];
            rs1 += sc[nt][2] + sc[nt][3];
        }
        rs0 += __shfl_xor_sync(0xffffffffu, rs0, 1);
        rs0 += __shfl_xor_sync(0xffffffffu, rs0, 2);
        rs1 += __shfl_xor_sync(0xffffffffu, rs1, 1);
        rs1 += __shfl_xor_sync(0xffffffffu, rs1, 2);

        float corr0 = (act0 && m0 > -INFINITY) ? __expf(m0 - mn0) : (act0 ? 0.f : 1.f);
        float corr1 = (act1 && m1 > -INFINITY) ? __expf(m1 - mn1) : (act1 ? 0.f : 1.f);
        l0 = l0 * corr0 + rs0;  m0 = mn0;
        l1 = l1 * corr1 + rs1;  m1 = mn1;
        #pragma unroll
        for (int nt = 0; nt < 16; nt++) {
            oacc[nt][0] *= corr0; oacc[nt][1] *= corr0;
            oacc[nt][2] *= corr1; oacc[nt][3] *= corr1;
        }

        #pragma unroll
        for (int nt = 0; nt < 4; nt++) {
            int wn_ = nt * 4 + lc;
            int pos = ((wn_ & 8) | kperm8(wn_ & 7)) * 2;
            *(__half2*)(pw + lr * 48 + pos)       = __floats2half2_rn(sc[nt][0], sc[nt][1]);
            *(__half2*)(pw + (lr + 8) * 48 + pos) = __floats2half2_rn(sc[nt][2], sc[nt][3]);
        }
        __syncwarp();

        #pragma unroll
        for (int kc = 0; kc < 2; kc++) {
            const int fo = kc * 16 + 4 * lc;
            uint2 p0 = *(const uint2*)(pw + lr * 48 + fo);
            uint2 p1 = *(const uint2*)(pw + (lr + 8) * 48 + fo);
            uint32_t a[4] = { p0.x, p1.x, p0.y, p1.y };
            #pragma unroll
            for (int nt = 0; nt < 16; nt++) {
                uint2 g = *(const uint2*)(vs + (nt * 8 + lr) * 48 + fo);
                uint32_t bb[2] = { g.x, g.y };
                mma_fp16(oacc[nt], a, bb);
            }
        }
        __syncwarp();
    }

    float inv0 = (l0 > 0.f) ? 1.f / l0 : 0.f;
    float inv1 = (l1 > 0.f) ? 1.f / l1 : 0.f;
    size_t row0 = (size_t)(b * SS + qA) * DD + h * HDN;
    size_t row1 = row0 + (size_t)8 * DD;
    #pragma unroll
    for (int nt = 0; nt < 16; nt++) {
        int corig = nt * 8 + 2 * lc;
        float2 r0, r1;
        if (l0 > 0.f) r0 = make_float2(oacc[nt][0] * inv0, oacc[nt][1] * inv0);
        else          r0 = make_float2(g_vmean[bn * HDN + corig], g_vmean[bn * HDN + corig + 1]);
        if (l1 > 0.f) r1 = make_float2(oacc[nt][2] * inv1, oacc[nt][3] * inv1);
        else          r1 = make_float2(g_vmean[bn * HDN + corig], g_vmean[bn * HDN + corig + 1]);
        *(__half2*)&g_oh[row0 + corig] = __floats2half2_rn(r0.x, r0.y);
        *(__half2*)&g_oh[row1 + corig] = __floats2half2_rn(r1.x, r1.y);
    }
}

// ---------------- launch -----------------------------------------------------
extern "C" void kernel_launch(void* const* d_in, const int* in_sizes, int n_in,
                              void* d_out, int out_size) {
    const float* X  = (const float*)d_in[0];
    const float* Wq = (const float*)d_in[1];
    const float* Wk = (const float*)d_in[2];
    const float* Wv = (const float*)d_in[3];
    const float* Wg = (const float*)d_in[4];
    const float* Wd = (const float*)d_in[5];
    const float* Wo = (const float*)d_in[6];
    float* out = (float*)d_out;

    float *qkvp;
    __half *xh, *wbTh, *woTh, *oh;
    cudaGetSymbolAddress((void**)&qkvp, g_qkv);
    cudaGetSymbolAddress((void**)&xh,   g_xh);
    cudaGetSymbolAddress((void**)&wbTh, g_wbTh);
    cudaGetSymbolAddress((void**)&woTh, g_woTh);
    cudaGetSymbolAddress((void**)&oh,   g_oh);

    cudaFuncSetAttribute(gemm_fp16, cudaFuncAttributeMaxDynamicSharedMemorySize, GEMM_SMEM);
    cudaFuncSetAttribute(attn_mma, cudaFuncAttributeMaxDynamicSharedMemorySize, ATTN_SMEM);
    cudaFuncSetAttribute(prep_x2, cudaFuncAttributeMaxDynamicSharedMemorySize, PX_SMEM);

    fuse_both<<<512, 256>>>(Wq, Wg, Wv, Wd);                                 // 0
    transpose_wb<<<dim3(NQKV / 32, DD / 32), 256>>>(Wq, Wk, Wv);             // 1
    transpose_wo<<<dim3(DD / 32, DD / 32), 256>>>(Wo);                       // 2
    prep_x2<<<MROWS / PXROWS, 256, PX_SMEM>>>(X);                            // 3 (ncu -s 5)
    gemm_fp16<<<dim3(NQKV / 128, MROWS / 128), 256, GEMM_SMEM>>>(            // 4
        xh, wbTh, qkvp, MROWS, NQKV, DD);

    vmean_part<<<dim3(8, BB * HKVN), HDN>>>();
    vmean_fin<<<BB * HKVN, HDN>>>();

    scan_kernel<<<BB * HKVN, 1024>>>();
    gather_kernel<<<dim3(SS / 8, BB * HKVN), 256>>>();
    pad_kernel<<<BB * HKVN, 1024>>>();
    vtrans_kernel<<<dim3(CAP / 32, HDN / 32, BB * HKVN), 256>>>();

    attn_mma<<<dim3(SS / QB, HH, BB), 256, ATTN_SMEM>>>();

    gemm_fp16<<<dim3(DD / 128, MROWS / 128), 256, GEMM_SMEM>>>(oh, woTh, out, MROWS, DD, DD);
}

// round 16
// speedup vs baseline: 1.1008x; 1.1008x over previous
#include <cuda_runtime.h>
#include <cuda_fp16.h>
#include <math.h>
#include <stdint.h>

#define BB   2
#define SS   2048
#define DD   2048
#define HH   16
#define HKVN 4
#define HDN  128
#define MROWS (BB*SS)
#define NQKV 3072            // Q(2048) | K(512) | V(512)
#define CAP  (SS+32)

// ---------------- scratch ----------------------------------------------------
__device__ float  g_qkv[MROWS*NQKV];     // fused projections (fp32, standard layout)
__device__ float  g_bias[BB*HKVN*SS];
__device__ float  g_vmean[BB*HKVN*HDN];
__device__ float  g_vpart[8*8*HDN];
__device__ __half g_oh[MROWS*DD];        // attention out, fp16, NATURAL k order
__device__ __half g_xh[MROWS*DD];        // fp16 X, NATURAL k order
__device__ __half g_wbTh[NQKV*DD];       // [Wq|Wk|Wv]^T K-major, natural, fp16
__device__ __half g_woTh[DD*DD];         // Wo^T K-major, natural, fp16
__device__ float  g_wqg[DD*HKVN];
__device__ float  g_wvd[DD*HKVN];
__device__ __half g_ckh[BB*HKVN*CAP*HDN];  // compacted K, fp16, d pair-permuted
__device__ float  g_cv[BB*HKVN*CAP*HDN];   // compacted V, fp32 (vtrans input)
__device__ __half g_cvth[BB*HKVN*HDN*CAP]; // V^T [bn][d][key], fp16, key-permuted
__device__ float  g_cb[BB*HKVN*CAP];
__device__ int    g_cidx[BB*HKVN*CAP];
__device__ int    g_prefix[BB*HKVN*(SS+1)];

__device__ __forceinline__ void mma_fp16(float* c, const uint32_t* a, const uint32_t* b) {
    asm volatile(
        "mma.sync.aligned.m16n8k16.row.col.f32.f16.f16.f32 "
        "{%0,%1,%2,%3},{%4,%5,%6,%7},{%8,%9},{%0,%1,%2,%3};"
        : "+f"(c[0]), "+f"(c[1]), "+f"(c[2]), "+f"(c[3])
        : "r"(a[0]), "r"(a[1]), "r"(a[2]), "r"(a[3]), "r"(b[0]), "r"(b[1]));
}
__device__ __forceinline__ void ldsm_x4(uint32_t* r, uint32_t addr) {
    asm volatile("ldmatrix.sync.aligned.m8n8.x4.shared.b16 {%0,%1,%2,%3}, [%4];"
        : "=r"(r[0]), "=r"(r[1]), "=r"(r[2]), "=r"(r[3]) : "r"(addr));
}
#define CP16(dst, src) asm volatile("cp.async.cg.shared.global [%0], [%1], 16;" :: "r"(dst), "l"(src))

// pair-permutation of 32-bit words within 8-word groups (attention internal)
__device__ __forceinline__ int kperm8(int j) { return (j < 4) ? 2 * j : 2 * j - 7; }
__device__ __forceinline__ int kph(int j) {
    return (j & 16) | (kperm8((j >> 1) & 7) << 1) | (j & 1);
}

// ---------------- transpose + fp16 (natural): wbTh from Wq|Wk|Wv ------------
__global__ void transpose_wb(const float* __restrict__ Wq, const float* __restrict__ Wk,
                             const float* __restrict__ Wv) {
    __shared__ float t[32][33];
    int n0 = blockIdx.x * 32, k0 = blockIdx.y * 32;
    int tx = threadIdx.x & 31, ty = threadIdx.x >> 5;
    const float* src; int sN, scol;
    if (n0 < 2048)      { src = Wq; sN = 2048; scol = n0; }
    else if (n0 < 2560) { src = Wk; sN = 512;  scol = n0 - 2048; }
    else                { src = Wv; sN = 512;  scol = n0 - 2560; }
    #pragma unroll
    for (int i = 0; i < 32; i += 8)
        t[ty + i][tx] = src[(size_t)(k0 + ty + i) * sN + scol + tx];
    __syncthreads();
    #pragma unroll
    for (int i = 0; i < 32; i += 8)
        g_wbTh[(size_t)(n0 + ty + i) * DD + k0 + tx] = __float2half_rn(t[tx][ty + i]);
}

__global__ void transpose_wo(const float* __restrict__ Wo) {
    __shared__ float t[32][33];
    int n0 = blockIdx.x * 32, k0 = blockIdx.y * 32;
    int tx = threadIdx.x & 31, ty = threadIdx.x >> 5;
    #pragma unroll
    for (int i = 0; i < 32; i += 8)
        t[ty + i][tx] = Wo[(size_t)(k0 + ty + i) * DD + n0 + tx];
    __syncthreads();
    #pragma unroll
    for (int i = 0; i < 32; i += 8)
        g_woTh[(size_t)(n0 + ty + i) * DD + k0 + tx] = __float2half_rn(t[tx][ty + i]);
}

// ---------------- fused small weights ----------------------------------------
__global__ void fuse_both(const float* __restrict__ Wq, const float* __restrict__ Wg,
                          const float* __restrict__ Wv, const float* __restrict__ Wd) {
    int half_ = gridDim.x >> 1;
    const float* A; const float* B; float* out; int K;
    int blk = blockIdx.x;
    if (blk < half_) { A = Wq; B = Wg; out = g_wqg; K = DD; }
    else             { A = Wv; B = Wd; out = g_wvd; K = HKVN * HDN; blk -= half_; }
    int d    = (blk * blockDim.x + threadIdx.x) >> 5;
    int lane = threadIdx.x & 31;
    if (d >= DD) return;
    float a0 = 0.f, a1 = 0.f, a2 = 0.f, a3 = 0.f;
    const float* ar = A + (size_t)d * K;
    for (int j = lane; j < K; j += 32) {
        float a = ar[j];
        float4 b = *(const float4*)&B[j * 4];
        a0 += a * b.x; a1 += a * b.y; a2 += a * b.z; a3 += a * b.w;
    }
    #pragma unroll
    for (int off = 16; off; off >>= 1) {
        a0 += __shfl_xor_sync(0xffffffffu, a0, off);
        a1 += __shfl_xor_sync(0xffffffffu, a1, off);
        a2 += __shfl_xor_sync(0xffffffffu, a2, off);
        a3 += __shfl_xor_sync(0xffffffffu, a3, off);
    }
    if (lane == 0) { *(float4*)&out[d * 4] = make_float4(a0, a1, a2, a3); }
}

// ---------------- prep X v3: weights in REGISTERS, 8 rows/block -------------
// Per-row math byte-identical to round-14 prep_x (same thread mapping, same
// j-loop, same shfl and block reduction order) -> bias bits unchanged.
// Weight loads amortized 8x via register residency.
#define PXR 8

__global__ void prep_x3(const float* __restrict__ X) {
    __shared__ float red[8][8];
    const int tid = threadIdx.x;
    const int lane = tid & 31, w = tid >> 5;

    // load this thread's weight slice once (d = tid*8 .. tid*8+7)
    float4 wg4[8], wd4[8];
    #pragma unroll
    for (int j = 0; j < 8; j++) {
        int d = tid * 8 + j;
        wg4[j] = *(const float4*)&g_wqg[d * 4];
        wd4[j] = *(const float4*)&g_wvd[d * 4];
    }

    #pragma unroll 1
    for (int rr = 0; rr < PXR; rr++) {
        const int row = blockIdx.x * PXR + rr;
        const float* xrow = X + (size_t)row * DD;
        float4 v0 = *(const float4*)(xrow + tid * 8);
        float4 v1 = *(const float4*)(xrow + tid * 8 + 4);
        float xs[8] = {v0.x, v0.y, v0.z, v0.w, v1.x, v1.y, v1.z, v1.w};
        float sg[4] = {0,0,0,0}, sd[4] = {0,0,0,0};
        #pragma unroll
        for (int j = 0; j < 8; j++) {
            float4 wg = wg4[j];
            float4 wv = wd4[j];
            sg[0] += xs[j]*wg.x; sg[1] += xs[j]*wg.y; sg[2] += xs[j]*wg.z; sg[3] += xs[j]*wg.w;
            sd[0] += xs[j]*wv.x; sd[1] += xs[j]*wv.y; sd[2] += xs[j]*wv.z; sd[3] += xs[j]*wv.w;
        }
        {   // natural fp16 store, one 16B write
            __half2 h[4];
            #pragma unroll
            for (int i = 0; i < 4; i++) h[i] = __floats2half2_rn(xs[2 * i], xs[2 * i + 1]);
            *(uint4*)&g_xh[(size_t)row * DD + tid * 8] = *(uint4*)h;
        }
        #pragma unroll
        for (int off = 16; off; off >>= 1)
            #pragma unroll
            for (int n = 0; n < 4; n++) {
                sg[n] += __shfl_xor_sync(0xffffffffu, sg[n], off);
                sd[n] += __shfl_xor_sync(0xffffffffu, sd[n], off);
            }
        if (lane == 0) {
            red[w][0] = sg[0]; red[w][1] = sg[1]; red[w][2] = sg[2]; red[w][3] = sg[3];
            red[w][4] = sd[0]; red[w][5] = sd[1]; red[w][6] = sd[2]; red[w][7] = sd[3];
        }
        __syncthreads();
        if (tid < 8) {
            float a = 0.f;
            #pragma unroll
            for (int ww = 0; ww < 8; ww++) a += red[ww][tid];
            red[0][tid] = a;
        }
        __syncthreads();
        if (tid < 4) {
            int b = row / SS, s = row % SS;
            g_bias[(b * HKVN + tid) * SS + s] = red[0][tid + 4] / (1.f + expf(-red[0][tid]));
        }
        __syncthreads();
    }
}

// ---------------- fp16 GEMM with ldmatrix fragment loads --------------------
#define BKH 64
#define STAGE_H (128*BKH)
#define NSTAGE 3
#define GEMM_SMEM (NSTAGE*2*STAGE_H*2)

__global__ __launch_bounds__(256, 2) void gemm_fp16(const __half* __restrict__ A,
                                                    const __half* __restrict__ B,
                                                    float* __restrict__ C,
                                                    int M, int N, int K) {
    extern __shared__ __half smh[];
    __half* As = smh;
    __half* Bs = smh + NSTAGE * STAGE_H;

    const int tid  = threadIdx.x;
    const int wid  = tid >> 5;
    const int lane = tid & 31;
    const int wm   = (wid & 3) << 5;
    const int wn   = (wid >> 2) << 6;
    const int m0   = blockIdx.y << 7;
    const int n0   = blockIdx.x << 7;
    const int lr   = lane >> 2;
    const int lc   = lane & 3;

    const int aRow0 = wm + (lane & 15);
    const int aCS   = lane >> 4;
    const int bRowB = wn + (((lane >> 4) & 1) << 3) + (lane & 7);
    const int bCS   = (lane >> 3) & 1;

    float acc[2][8][4];
    #pragma unroll
    for (int mt = 0; mt < 2; mt++)
        #pragma unroll
        for (int nt = 0; nt < 8; nt++)
            #pragma unroll
            for (int i = 0; i < 4; i++) acc[mt][nt][i] = 0.f;

    const int KT = K >> 6;

    auto load_stage = [&](int kt, int s) {
        __half* as = As + s * STAGE_H;
        __half* bs = Bs + s * STAGE_H;
        #pragma unroll
        for (int p = 0; p < 4; p++) {
            int idx = tid + (p << 8);
            int r = idx >> 3, c = idx & 7;
            uint32_t slot = (uint32_t)(c ^ (r & 7));
            CP16((uint32_t)__cvta_generic_to_shared(as + r * BKH + slot * 8),
                 A + (size_t)(m0 + r) * K + (kt << 6) + c * 8);
        }
        #pragma unroll
        for (int p = 0; p < 4; p++) {
            int idx = tid + (p << 8);
            int r = idx >> 3, c = idx & 7;
            uint32_t slot = (uint32_t)(c ^ (r & 7));
            CP16((uint32_t)__cvta_generic_to_shared(bs + r * BKH + slot * 8),
                 B + (size_t)(n0 + r) * K + (kt << 6) + c * 8);
        }
        asm volatile("cp.async.commit_group;");
    };

    load_stage(0, 0);
    if (KT > 1) load_stage(1, 1);

    int sc_ = 0;
    int sl_ = 2 % NSTAGE;

    for (int kt = 0; kt < KT; kt++) {
        if (kt + 2 < KT) { asm volatile("cp.async.wait_group 1;"); }
        else             { asm volatile("cp.async.wait_group 0;"); }
        __syncthreads();
        if (kt + 2 < KT) {
            load_stage(kt + 2, sl_);
            sl_ = (sl_ + 1 == NSTAGE) ? 0 : sl_ + 1;
        }

        uint32_t asb = (uint32_t)__cvta_generic_to_shared(As + sc_ * STAGE_H);
        uint32_t bsb = (uint32_t)__cvta_generic_to_shared(Bs + sc_ * STAGE_H);
        sc_ = (sc_ + 1 == NSTAGE) ? 0 : sc_ + 1;

        #pragma unroll
        for (int ks = 0; ks < 4; ks++) {
            uint32_t afr[2][4];
            #pragma unroll
            for (int mt = 0; mt < 2; mt++) {
                int row = aRow0 + (mt << 4);
                uint32_t addr = asb + row * 128 + ((((ks << 1) + aCS) ^ (row & 7)) << 4);
                ldsm_x4(afr[mt], addr);
            }
            #pragma unroll
            for (int ntp = 0; ntp < 4; ntp++) {
                int row = bRowB + (ntp << 4);
                uint32_t addr = bsb + row * 128 + ((((ks << 1) + bCS) ^ (row & 7)) << 4);
                uint32_t b4[4];
                ldsm_x4(b4, addr);
                mma_fp16(acc[0][2 * ntp],     afr[0], b4);
                mma_fp16(acc[1][2 * ntp],     afr[1], b4);
                mma_fp16(acc[0][2 * ntp + 1], afr[0], b4 + 2);
                mma_fp16(acc[1][2 * ntp + 1], afr[1], b4 + 2);
            }
        }
    }

    #pragma unroll
    for (int mt = 0; mt < 2; mt++) {
        #pragma unroll
        for (int nt = 0; nt < 8; nt++) {
            int row = m0 + wm + (mt << 4) + lr;
            int col = n0 + wn + (nt << 3) + (lc << 1);
            *(float2*)&C[(size_t)row * N + col] =
                make_float2(acc[mt][nt][0], acc[mt][nt][1]);
            *(float2*)&C[(size_t)(row + 8) * N + col] =
                make_float2(acc[mt][nt][2], acc[mt][nt][3]);
        }
    }
}

// ---------------- vmean (two-phase) ------------------------------------------
__global__ void vmean_part() {
    int ch = blockIdx.x, bn = blockIdx.y, d = threadIdx.x;
    int b = bn >> 2, n = bn & 3;
    float s = 0.f;
    int r0 = ch * 256;
    #pragma unroll 4
    for (int t = 0; t < 256; t++)
        s += g_qkv[(size_t)(b * SS + r0 + t) * NQKV + 2560 + n * HDN + d];
    g_vpart[(bn * 8 + ch) * HDN + d] = s;
}
__global__ void vmean_fin() {
    int bn = blockIdx.x, d = threadIdx.x;
    float s = 0.f;
    #pragma unroll
    for (int ch = 0; ch < 8; ch++) s += g_vpart[(bn * 8 + ch) * HDN + d];
    g_vmean[bn * HDN + d] = s * (1.f / SS);
}

// ---------------- compaction -------------------------------------------------
__global__ void scan_kernel() {
    __shared__ int wsum[32];
    int bn = blockIdx.x, t = threadIdx.x;
    int lane = t & 31, w = t >> 5;
    const float* bias = g_bias + bn * SS;
    int f0 = bias[2 * t]     > 0.f;
    int f1 = bias[2 * t + 1] > 0.f;
    int v = f0 + f1;
    int s = v;
    #pragma unroll
    for (int off = 1; off < 32; off <<= 1) {
        int u = __shfl_up_sync(0xffffffffu, s, off);
        if (lane >= off) s += u;
    }
    if (lane == 31) wsum[w] = s;
    __syncthreads();
    if (w == 0) {
        int ws = wsum[lane];
        #pragma unroll
        for (int off = 1; off < 32; off <<= 1) {
            int u = __shfl_up_sync(0xffffffffu, ws, off);
            if (lane >= off) ws += u;
        }
        wsum[lane] = ws;
    }
    __syncthreads();
    int base = (w > 0 ? wsum[w - 1] : 0) + s - v;
    int* pf = g_prefix + bn * (SS + 1);
    if (t == 0) pf[0] = 0;
    pf[2 * t + 1] = base + f0;
    pf[2 * t + 2] = base + f0 + f1;
}

__global__ void gather_kernel() {
    int bn = blockIdx.y;
    int b = bn >> 2, n = bn & 3;
    int w = threadIdx.x >> 5, lane = threadIdx.x & 31;
    int key = blockIdx.x * 8 + w;
    float bk = g_bias[bn * SS + key];
    if (bk > 0.f) {
        int pos = g_prefix[bn * (SS + 1) + key];
        size_t src = (size_t)(b * SS + key) * NQKV + 2048 + n * HDN + lane * 4;
        float4 kv = *(const float4*)(g_qkv + src);
        float4 vv = *(const float4*)(g_qkv + src + 512);
        int w0 = 2 * lane, w1 = w0 + 1;
        int p0 = (w0 & 56) | kperm8(w0 & 7);
        int p1 = (w1 & 56) | kperm8(w1 & 7);
        __half* kdst = g_ckh + ((size_t)bn * CAP + pos) * HDN;
        *(__half2*)(kdst + p0 * 2) = __floats2half2_rn(kv.x, kv.y);
        *(__half2*)(kdst + p1 * 2) = __floats2half2_rn(kv.z, kv.w);
        *(float4*)(g_cv + ((size_t)bn * CAP + pos) * HDN + lane * 4) = vv;
        if (lane == 0) { g_cb[bn * CAP + pos] = bk; g_cidx[bn * CAP + pos] = key; }
    }
}

__global__ void pad_kernel() {
    int bn = blockIdx.x;
    int nc = g_prefix[bn * (SS + 1) + SS];
    int r = threadIdx.x >> 5, lane = threadIdx.x & 31;
    int pos = nc + r;
    __half* kdst = g_ckh + ((size_t)bn * CAP + pos) * HDN + lane * 4;
    *(__half2*)(kdst)     = __floats2half2_rn(0.f, 0.f);
    *(__half2*)(kdst + 2) = __floats2half2_rn(0.f, 0.f);
    *(float4*)(g_cv + ((size_t)bn * CAP + pos) * HDN + lane * 4) = make_float4(0.f,0.f,0.f,0.f);
    if (lane == 0) { g_cidx[bn * CAP + pos] = 0x7fffffff; g_cb[bn * CAP + pos] = 0.f; }
}

// ---------------- vtrans: V^T [bn][d][key] fp16, key pair-permuted ----------
__global__ void vtrans_kernel() {
    __shared__ float t[32][33];
    int k0 = blockIdx.x * 32, d0 = blockIdx.y * 32, bn = blockIdx.z;
    int tx = threadIdx.x & 31, ty = threadIdx.x >> 5;
    #pragma unroll
    for (int i = 0; i < 32; i += 8)
        t[ty + i][tx] = g_cv[((size_t)bn * CAP + k0 + ty + i) * HDN + d0 + tx];
    __syncthreads();
    int kp = kph(tx);
    #pragma unroll
    for (int i = 0; i < 32; i += 8)
        g_cvth[((size_t)bn * HDN + d0 + ty + i) * CAP + k0 + kp] =
            __float2half_rn(t[tx][ty + i]);
}

// ---------------- fp16 tensor-core flash attention ---------------------------
#define QB   128
#define KB   32
#define Q_SH   (256*64)
#define K_SH   (64*64)
#define VT_SH  (128*48)
#define P_SH   (16*48)
#define ATTN_SMEM ((Q_SH + 2*K_SH + 2*VT_SH + 8*P_SH)*2 + 512)

__global__ __launch_bounds__(256) void attn_mma() {
    extern __shared__ __half sha[];
    __half* q_sh  = sha;
    __half* k_sh  = q_sh + Q_SH;
    __half* vt_sh = k_sh + 2 * K_SH;
    __half* p_sh  = vt_sh + 2 * VT_SH;
    float*  cb_sh = (float*)(p_sh + 8 * P_SH);
    int*    idx_sh = (int*)(cb_sh + 64);

    const int qblk = (gridDim.x - 1) - blockIdx.x;
    const int h    = blockIdx.y;
    const int b    = blockIdx.z;
    const int n    = h >> 2;
    const int bn   = b * HKVN + n;
    const int q0   = qblk * QB;
    const int tid  = threadIdx.x;
    const int w    = tid >> 5;
    const int lane = tid & 31;
    const int lr   = lane >> 2;
    const int lc   = lane & 3;
    const float scale = 0.08838834764831843f;

    {
        int qrow = tid >> 1;
        int sub  = tid & 1;
        int rr   = (qrow << 1) | sub;
        const float* src = g_qkv + (size_t)(b * SS + q0 + qrow) * NQKV + h * HDN + (sub << 6);
        __half* dst = q_sh + rr * 64;
        int xw = (rr & 3) << 3;
        #pragma unroll
        for (int j = 0; j < 16; j++) {
            float4 v = *(const float4*)(src + j * 4);
            int w0 = 2 * j, w1 = w0 + 1;
            int pp0 = (((w0 & 24) | kperm8(w0 & 7)) ^ xw);
            int pp1 = (((w1 & 24) | kperm8(w1 & 7)) ^ xw);
            *(__half2*)(dst + pp0 * 2) = __floats2half2_rn(v.x * scale, v.y * scale);
            *(__half2*)(dst + pp1 * 2) = __floats2half2_rn(v.z * scale, v.w * scale);
        }
    }

    const int limit  = g_prefix[bn * (SS + 1) + q0 + QB];
    const int ntiles = (limit + KB - 1) / KB;

    auto load_tile = [&](int kt, int st) {
        __half* ks = k_sh + st * K_SH;
        __half* vs = vt_sh + st * VT_SH;
        const __half* kg = g_ckh + ((size_t)bn * CAP + kt * KB) * HDN;
        #pragma unroll
        for (int p = 0; p < 2; p++) {
            int id = tid + (p << 8);
            int r = id >> 3, c = id & 7;
            uint32_t slot = (uint32_t)((2 * c) ^ ((r & 3) << 2));
            CP16((uint32_t)__cvta_generic_to_shared(ks + r * 64 + slot * 4),
                 kg + (size_t)(r >> 1) * HDN + ((r & 1) << 6) + c * 8);
        }
        #pragma unroll
        for (int p = 0; p < 2; p++) {
            int id = tid + (p << 8);
            int r = id >> 2, c = id & 3;
            CP16((uint32_t)__cvta_generic_to_shared(vs + r * 48 + c * 8),
                 g_cvth + ((size_t)bn * HDN + r) * CAP + kt * KB + c * 8);
        }
        if (tid < 8)
            CP16((uint32_t)__cvta_generic_to_shared(cb_sh + st * 32 + tid * 4),
                 g_cb + bn * CAP + kt * KB + tid * 4);
        else if (tid < 16)
            CP16((uint32_t)__cvta_generic_to_shared(idx_sh + st * 32 + (tid - 8) * 4),
                 g_cidx + bn * CAP + kt * KB + (tid - 8) * 4);
        asm volatile("cp.async.commit_group;");
    };

    float m0 = -INFINITY, m1 = -INFINITY, l0 = 0.f, l1 = 0.f;
    float oacc[16][4];
    #pragma unroll
    for (int nt = 0; nt < 16; nt++)
        #pragma unroll
        for (int i = 0; i < 4; i++) oacc[nt][i] = 0.f;

    const int qA = q0 + w * 16 + lr;
    __half* pw = p_sh + w * P_SH;

    if (ntiles > 0) load_tile(0, 0);

    for (int kt = 0; kt < ntiles; kt++) {
        const int st = kt & 1;
        asm volatile("cp.async.wait_group 0;");
        __syncthreads();
        if (kt + 1 < ntiles) load_tile(kt + 1, st ^ 1);

        const __half* ks = k_sh + st * K_SH;
        const __half* vs = vt_sh + st * VT_SH;
        const float*  cb = cb_sh + st * 32;
        const int*    ix = idx_sh + st * 32;

        float sc[4][4];
        #pragma unroll
        for (int nt = 0; nt < 4; nt++)
            #pragma unroll
            for (int i = 0; i < 4; i++) sc[nt][i] = 0.f;

        #pragma unroll
        for (int kc = 0; kc < 8; kc++) {
            const int dhi = kc >> 2, ksx = kc & 3;
            const int t3 = (2 * lr + dhi) & 3;
            const int fo = (4 * (ksx ^ t3) + lc) * 4;
            const int rr0 = (w << 5) + 2 * lr + dhi;
            uint2 f0 = *(const uint2*)(q_sh + rr0 * 64 + fo);
            uint2 f1 = *(const uint2*)(q_sh + (rr0 + 16) * 64 + fo);
            uint32_t a[4] = { f0.x, f1.x, f0.y, f1.y };
            #pragma unroll
            for (int nt = 0; nt < 4; nt++) {
                int kr = (nt << 4) + 2 * lr + dhi;
                uint2 g = *(const uint2*)(ks + kr * 64 + fo);
                uint32_t bb[2] = { g.x, g.y };
                mma_fp16(sc[nt], a, bb);
            }
        }

        #pragma unroll
        for (int nt = 0; nt < 4; nt++) {
            int c0 = nt * 8 + 2 * lc, c1 = c0 + 1;
            float bk0 = cb[c0], bk1 = cb[c1];
            int   i0  = ix[c0], i1  = ix[c1];
            sc[nt][0] = (i0 <= qA)     ? sc[nt][0] + bk0 : -INFINITY;
            sc[nt][1] = (i1 <= qA)     ? sc[nt][1] + bk1 : -INFINITY;
            sc[nt][2] = (i0 <= qA + 8) ? sc[nt][2] + bk0 : -INFINITY;
            sc[nt][3] = (i1 <= qA + 8) ? sc[nt][3] + bk1 : -INFINITY;
        }

        float tm0 = -INFINITY, tm1 = -INFINITY;
        #pragma unroll
        for (int nt = 0; nt < 4; nt++) {
            tm0 = fmaxf(tm0, fmaxf(sc[nt][0], sc[nt][1]));
            tm1 = fmaxf(tm1, fmaxf(sc[nt][2], sc[nt][3]));
        }
        tm0 = fmaxf(tm0, __shfl_xor_sync(0xffffffffu, tm0, 1));
        tm0 = fmaxf(tm0, __shfl_xor_sync(0xffffffffu, tm0, 2));
        tm1 = fmaxf(tm1, __shfl_xor_sync(0xffffffffu, tm1, 1));
        tm1 = fmaxf(tm1, __shfl_xor_sync(0xffffffffu, tm1, 2));
        float mn0 = fmaxf(m0, tm0), mn1 = fmaxf(m1, tm1);
        bool act0 = (mn0 > -INFINITY), act1 = (mn1 > -INFINITY);

        float rs0 = 0.f, rs1 = 0.f;
        #pragma unroll
        for (int nt = 0; nt < 4; nt++) {
            sc[nt][0] = act0 ? __expf(sc[nt][0] - mn0) : 0.f;
            sc[nt][1] = act0 ? __expf(sc[nt][1] - mn0) : 0.f;
            sc[nt][2] = act1 ? __expf(sc[nt][2] - mn1) : 0.f;
            sc[nt][3] = act1 ? __expf(sc[nt][3] - mn1) : 0.f;
            rs0 += sc[nt][0] + sc[nt][1];
            rs1 += sc[nt][2] + sc[nt][3];
        }
        rs0 += __shfl_xor_sync(0xffffffffu, rs0, 1);
        rs0 += __shfl_xor_sync(0xffffffffu, rs0, 2);
        rs1 += __shfl_xor_sync(0xffffffffu, rs1, 1);
        rs1 += __shfl_xor_sync(0xffffffffu, rs1, 2);

        float corr0 = (act0 && m0 > -INFINITY) ? __expf(m0 - mn0) : (act0 ? 0.f : 1.f);
        float corr1 = (act1 && m1 > -INFINITY) ? __expf(m1 - mn1) : (act1 ? 0.f : 1.f);
        l0 = l0 * corr0 + rs0;  m0 = mn0;
        l1 = l1 * corr1 + rs1;  m1 = mn1;
        #pragma unroll
        for (int nt = 0; nt < 16; nt++) {
            oacc[nt][0] *= corr0; oacc[nt][1] *= corr0;
            oacc[nt][2] *= corr1; oacc[nt][3] *= corr1;
        }

        #pragma unroll
        for (int nt = 0; nt < 4; nt++) {
            int wn_ = nt * 4 + lc;
            int pos = ((wn_ & 8) | kperm8(wn_ & 7)) * 2;
            *(__half2*)(pw + lr * 48 + pos)       = __floats2half2_rn(sc[nt][0], sc[nt][1]);
            *(__half2*)(pw + (lr + 8) * 48 + pos) = __floats2half2_rn(sc[nt][2], sc[nt][3]);
        }
        __syncwarp();

        #pragma unroll
        for (int kc = 0; kc < 2; kc++) {
            const int fo = kc * 16 + 4 * lc;
            uint2 p0 = *(const uint2*)(pw + lr * 48 + fo);
            uint2 p1 = *(const uint2*)(pw + (lr + 8) * 48 + fo);
            uint32_t a[4] = { p0.x, p1.x, p0.y, p1.y };
            #pragma unroll
            for (int nt = 0; nt < 16; nt++) {
                uint2 g = *(const uint2*)(vs + (nt * 8 + lr) * 48 + fo);
                uint32_t bb[2] = { g.x, g.y };
                mma_fp16(oacc[nt], a, bb);
            }
        }
        __syncwarp();
    }

    float inv0 = (l0 > 0.f) ? 1.f / l0 : 0.f;
    float inv1 = (l1 > 0.f) ? 1.f / l1 : 0.f;
    size_t row0 = (size_t)(b * SS + qA) * DD + h * HDN;
    size_t row1 = row0 + (size_t)8 * DD;
    #pragma unroll
    for (int nt = 0; nt < 16; nt++) {
        int corig = nt * 8 + 2 * lc;
        float2 r0, r1;
        if (l0 > 0.f) r0 = make_float2(oacc[nt][0] * inv0, oacc[nt][1] * inv0);
        else          r0 = make_float2(g_vmean[bn * HDN + corig], g_vmean[bn * HDN + corig + 1]);
        if (l1 > 0.f) r1 = make_float2(oacc[nt][2] * inv1, oacc[nt][3] * inv1);
        else          r1 = make_float2(g_vmean[bn * HDN + corig], g_vmean[bn * HDN + corig + 1]);
        *(__half2*)&g_oh[row0 + corig] = __floats2half2_rn(r0.x, r0.y);
        *(__half2*)&g_oh[row1 + corig] = __floats2half2_rn(r1.x, r1.y);
    }
}

// ---------------- launch -----------------------------------------------------
extern "C" void kernel_launch(void* const* d_in, const int* in_sizes, int n_in,
                              void* d_out, int out_size) {
    const float* X  = (const float*)d_in[0];
    const float* Wq = (const float*)d_in[1];
    const float* Wk = (const float*)d_in[2];
    const float* Wv = (const float*)d_in[3];
    const float* Wg = (const float*)d_in[4];
    const float* Wd = (const float*)d_in[5];
    const float* Wo = (const float*)d_in[6];
    float* out = (float*)d_out;

    float *qkvp;
    __half *xh, *wbTh, *woTh, *oh;
    cudaGetSymbolAddress((void**)&qkvp, g_qkv);
    cudaGetSymbolAddress((void**)&xh,   g_xh);
    cudaGetSymbolAddress((void**)&wbTh, g_wbTh);
    cudaGetSymbolAddress((void**)&woTh, g_woTh);
    cudaGetSymbolAddress((void**)&oh,   g_oh);

    cudaFuncSetAttribute(gemm_fp16, cudaFuncAttributeMaxDynamicSharedMemorySize, GEMM_SMEM);
    cudaFuncSetAttribute(attn_mma, cudaFuncAttributeMaxDynamicSharedMemorySize, ATTN_SMEM);

    fuse_both<<<512, 256>>>(Wq, Wg, Wv, Wd);                                 // 0
    transpose_wb<<<dim3(NQKV / 32, DD / 32), 256>>>(Wq, Wk, Wv);             // 1
    transpose_wo<<<dim3(DD / 32, DD / 32), 256>>>(Wo);                       // 2
    prep_x3<<<MROWS / PXR, 256>>>(X);                                        // 3 (ncu -s 5)
    gemm_fp16<<<dim3(NQKV / 128, MROWS / 128), 256, GEMM_SMEM>>>(            // 4
        xh, wbTh, qkvp, MROWS, NQKV, DD);

    vmean_part<<<dim3(8, BB * HKVN), HDN>>>();
    vmean_fin<<<BB * HKVN, HDN>>>();

    scan_kernel<<<BB * HKVN, 1024>>>();
    gather_kernel<<<dim3(SS / 8, BB * HKVN), 256>>>();
    pad_kernel<<<BB * HKVN, 1024>>>();
    vtrans_kernel<<<dim3(CAP / 32, HDN / 32, BB * HKVN), 256>>>();

    attn_mma<<<dim3(SS / QB, HH, BB), 256, ATTN_SMEM>>>();

    gemm_fp16<<<dim3(DD / 128, MROWS / 128), 256, GEMM_SMEM>>>(oh, woTh, out, MROWS, DD, DD);
}

// round 17
// speedup vs baseline: 1.1103x; 1.0087x over previous
#include <cuda_runtime.h>
#include <cuda_fp16.h>
#include <math.h>
#include <stdint.h>

#define BB   2
#define SS   2048
#define DD   2048
#define HH   16
#define HKVN 4
#define HDN  128
#define MROWS (BB*SS)
#define NQKV 3072            // Q(2048) | K(512) | V(512)
#define CAP  (SS+32)

// ---------------- scratch ----------------------------------------------------
__device__ float  g_qkv[MROWS*NQKV];     // fused projections (fp32, standard layout)
__device__ float  g_bias[BB*HKVN*SS];
__device__ float  g_vmean[BB*HKVN*HDN];
__device__ __half g_oh[MROWS*DD];        // attention out, fp16, NATURAL k order
__device__ __half g_xh[MROWS*DD];        // fp16 X, NATURAL k order
__device__ __half g_wbTh[NQKV*DD];       // [Wq|Wk|Wv]^T K-major, natural, fp16
__device__ __half g_woTh[DD*DD];         // Wo^T K-major, natural, fp16
__device__ float  g_wqg[DD*HKVN];
__device__ float  g_wvd[DD*HKVN];
__device__ __half g_ckh[BB*HKVN*CAP*HDN];  // compacted K, fp16, d pair-permuted
__device__ __half g_cvh[BB*HKVN*CAP*HDN];  // compacted V, fp16, natural d
__device__ __half g_cvth[BB*HKVN*HDN*CAP]; // V^T [bn][d][key], fp16, key-permuted
__device__ float  g_cb[BB*HKVN*CAP];
__device__ int    g_cidx[BB*HKVN*CAP];
__device__ int    g_prefix[BB*HKVN*(SS+1)];

__device__ __forceinline__ void mma_fp16(float* c, const uint32_t* a, const uint32_t* b) {
    asm volatile(
        "mma.sync.aligned.m16n8k16.row.col.f32.f16.f16.f32 "
        "{%0,%1,%2,%3},{%4,%5,%6,%7},{%8,%9},{%0,%1,%2,%3};"
        : "+f"(c[0]), "+f"(c[1]), "+f"(c[2]), "+f"(c[3])
        : "r"(a[0]), "r"(a[1]), "r"(a[2]), "r"(a[3]), "r"(b[0]), "r"(b[1]));
}
__device__ __forceinline__ void ldsm_x4(uint32_t* r, uint32_t addr) {
    asm volatile("ldmatrix.sync.aligned.m8n8.x4.shared.b16 {%0,%1,%2,%3}, [%4];"
        : "=r"(r[0]), "=r"(r[1]), "=r"(r[2]), "=r"(r[3]) : "r"(addr));
}
#define CP16(dst, src) asm volatile("cp.async.cg.shared.global [%0], [%1], 16;" :: "r"(dst), "l"(src))

// pair-permutation of 32-bit words within 8-word groups (attention internal)
__device__ __forceinline__ int kperm8(int j) { return (j < 4) ? 2 * j : 2 * j - 7; }
__device__ __forceinline__ int kph(int j) {
    return (j & 16) | (kperm8((j >> 1) & 7) << 1) | (j & 1);
}

// ---------------- merged transpose + fp16: wbTh and woTh --------------------
__global__ void transpose_all(const float* __restrict__ Wq, const float* __restrict__ Wk,
                              const float* __restrict__ Wv, const float* __restrict__ Wo) {
    __shared__ float t[32][33];
    int bx = blockIdx.x;                 // 0..159: 0-95 wb, 96-159 wo
    int k0 = blockIdx.y * 32;
    int tx = threadIdx.x & 31, ty = threadIdx.x >> 5;
    const float* src; int sN, scol; __half* dstbase; int n0;
    if (bx < 96) {
        n0 = bx * 32; dstbase = g_wbTh;
        if (n0 < 2048)      { src = Wq; sN = 2048; scol = n0; }
        else if (n0 < 2560) { src = Wk; sN = 512;  scol = n0 - 2048; }
        else                { src = Wv; sN = 512;  scol = n0 - 2560; }
    } else {
        n0 = (bx - 96) * 32; dstbase = g_woTh;
        src = Wo; sN = 2048; scol = n0;
    }
    #pragma unroll
    for (int i = 0; i < 32; i += 8)
        t[ty + i][tx] = src[(size_t)(k0 + ty + i) * sN + scol + tx];
    __syncthreads();
    #pragma unroll
    for (int i = 0; i < 32; i += 8)
        dstbase[(size_t)(n0 + ty + i) * DD + k0 + tx] = __float2half_rn(t[tx][ty + i]);
}

// ---------------- fused small weights ----------------------------------------
__global__ void fuse_both(const float* __restrict__ Wq, const float* __restrict__ Wg,
                          const float* __restrict__ Wv, const float* __restrict__ Wd) {
    int half_ = gridDim.x >> 1;
    const float* A; const float* B; float* out; int K;
    int blk = blockIdx.x;
    if (blk < half_) { A = Wq; B = Wg; out = g_wqg; K = DD; }
    else             { A = Wv; B = Wd; out = g_wvd; K = HKVN * HDN; blk -= half_; }
    int d    = (blk * blockDim.x + threadIdx.x) >> 5;
    int lane = threadIdx.x & 31;
    if (d >= DD) return;
    float a0 = 0.f, a1 = 0.f, a2 = 0.f, a3 = 0.f;
    const float* ar = A + (size_t)d * K;
    for (int j = lane; j < K; j += 32) {
        float a = ar[j];
        float4 b = *(const float4*)&B[j * 4];
        a0 += a * b.x; a1 += a * b.y; a2 += a * b.z; a3 += a * b.w;
    }
    #pragma unroll
    for (int off = 16; off; off >>= 1) {
        a0 += __shfl_xor_sync(0xffffffffu, a0, off);
        a1 += __shfl_xor_sync(0xffffffffu, a1, off);
        a2 += __shfl_xor_sync(0xffffffffu, a2, off);
        a3 += __shfl_xor_sync(0xffffffffu, a3, off);
    }
    if (lane == 0) { *(float4*)&out[d * 4] = make_float4(a0, a1, a2, a3); }
}

// ---------------- prep X v3: weights in registers, 8 rows/block -------------
#define PXR 8

__global__ void prep_x3(const float* __restrict__ X) {
    __shared__ float red[8][8];
    const int tid = threadIdx.x;
    const int lane = tid & 31, w = tid >> 5;

    float4 wg4[8], wd4[8];
    #pragma unroll
    for (int j = 0; j < 8; j++) {
        int d = tid * 8 + j;
        wg4[j] = *(const float4*)&g_wqg[d * 4];
        wd4[j] = *(const float4*)&g_wvd[d * 4];
    }

    #pragma unroll 1
    for (int rr = 0; rr < PXR; rr++) {
        const int row = blockIdx.x * PXR + rr;
        const float* xrow = X + (size_t)row * DD;
        float4 v0 = *(const float4*)(xrow + tid * 8);
        float4 v1 = *(const float4*)(xrow + tid * 8 + 4);
        float xs[8] = {v0.x, v0.y, v0.z, v0.w, v1.x, v1.y, v1.z, v1.w};
        float sg[4] = {0,0,0,0}, sd[4] = {0,0,0,0};
        #pragma unroll
        for (int j = 0; j < 8; j++) {
            float4 wg = wg4[j];
            float4 wv = wd4[j];
            sg[0] += xs[j]*wg.x; sg[1] += xs[j]*wg.y; sg[2] += xs[j]*wg.z; sg[3] += xs[j]*wg.w;
            sd[0] += xs[j]*wv.x; sd[1] += xs[j]*wv.y; sd[2] += xs[j]*wv.z; sd[3] += xs[j]*wv.w;
        }
        {
            __half2 h[4];
            #pragma unroll
            for (int i = 0; i < 4; i++) h[i] = __floats2half2_rn(xs[2 * i], xs[2 * i + 1]);
            *(uint4*)&g_xh[(size_t)row * DD + tid * 8] = *(uint4*)h;
        }
        #pragma unroll
        for (int off = 16; off; off >>= 1)
            #pragma unroll
            for (int n = 0; n < 4; n++) {
                sg[n] += __shfl_xor_sync(0xffffffffu, sg[n], off);
                sd[n] += __shfl_xor_sync(0xffffffffu, sd[n], off);
            }
        if (lane == 0) {
            red[w][0] = sg[0]; red[w][1] = sg[1]; red[w][2] = sg[2]; red[w][3] = sg[3];
            red[w][4] = sd[0]; red[w][5] = sd[1]; red[w][6] = sd[2]; red[w][7] = sd[3];
        }
        __syncthreads();
        if (tid < 8) {
            float a = 0.f;
            #pragma unroll
            for (int ww = 0; ww < 8; ww++) a += red[ww][tid];
            red[0][tid] = a;
        }
        __syncthreads();
        if (tid < 4) {
            int b = row / SS, s = row % SS;
            g_bias[(b * HKVN + tid) * SS + s] = red[0][tid + 4] / (1.f + expf(-red[0][tid]));
        }
        __syncthreads();
    }
}

// ---------------- fp16 GEMM with ldmatrix fragment loads --------------------
#define BKH 64
#define STAGE_H (128*BKH)
#define NSTAGE 3
#define GEMM_SMEM (NSTAGE*2*STAGE_H*2)

__global__ __launch_bounds__(256, 2) void gemm_fp16(const __half* __restrict__ A,
                                                    const __half* __restrict__ B,
                                                    float* __restrict__ C,
                                                    int M, int N, int K) {
    extern __shared__ __half smh[];
    __half* As = smh;
    __half* Bs = smh + NSTAGE * STAGE_H;

    const int tid  = threadIdx.x;
    const int wid  = tid >> 5;
    const int lane = tid & 31;
    const int wm   = (wid & 3) << 5;
    const int wn   = (wid >> 2) << 6;
    const int m0   = blockIdx.y << 7;
    const int n0   = blockIdx.x << 7;
    const int lr   = lane >> 2;
    const int lc   = lane & 3;

    const int aRow0 = wm + (lane & 15);
    const int aCS   = lane >> 4;
    const int bRowB = wn + (((lane >> 4) & 1) << 3) + (lane & 7);
    const int bCS   = (lane >> 3) & 1;

    float acc[2][8][4];
    #pragma unroll
    for (int mt = 0; mt < 2; mt++)
        #pragma unroll
        for (int nt = 0; nt < 8; nt++)
            #pragma unroll
            for (int i = 0; i < 4; i++) acc[mt][nt][i] = 0.f;

    const int KT = K >> 6;

    auto load_stage = [&](int kt, int s) {
        __half* as = As + s * STAGE_H;
        __half* bs = Bs + s * STAGE_H;
        #pragma unroll
        for (int p = 0; p < 4; p++) {
            int idx = tid + (p << 8);
            int r = idx >> 3, c = idx & 7;
            uint32_t slot = (uint32_t)(c ^ (r & 7));
            CP16((uint32_t)__cvta_generic_to_shared(as + r * BKH + slot * 8),
                 A + (size_t)(m0 + r) * K + (kt << 6) + c * 8);
        }
        #pragma unroll
        for (int p = 0; p < 4; p++) {
            int idx = tid + (p << 8);
            int r = idx >> 3, c = idx & 7;
            uint32_t slot = (uint32_t)(c ^ (r & 7));
            CP16((uint32_t)__cvta_generic_to_shared(bs + r * BKH + slot * 8),
                 B + (size_t)(n0 + r) * K + (kt << 6) + c * 8);
        }
        asm volatile("cp.async.commit_group;");
    };

    load_stage(0, 0);
    if (KT > 1) load_stage(1, 1);

    int sc_ = 0;
    int sl_ = 2 % NSTAGE;

    for (int kt = 0; kt < KT; kt++) {
        if (kt + 2 < KT) { asm volatile("cp.async.wait_group 1;"); }
        else             { asm volatile("cp.async.wait_group 0;"); }
        __syncthreads();
        if (kt + 2 < KT) {
            load_stage(kt + 2, sl_);
            sl_ = (sl_ + 1 == NSTAGE) ? 0 : sl_ + 1;
        }

        uint32_t asb = (uint32_t)__cvta_generic_to_shared(As + sc_ * STAGE_H);
        uint32_t bsb = (uint32_t)__cvta_generic_to_shared(Bs + sc_ * STAGE_H);
        sc_ = (sc_ + 1 == NSTAGE) ? 0 : sc_ + 1;

        #pragma unroll
        for (int ks = 0; ks < 4; ks++) {
            uint32_t afr[2][4];
            #pragma unroll
            for (int mt = 0; mt < 2; mt++) {
                int row = aRow0 + (mt << 4);
                uint32_t addr = asb + row * 128 + ((((ks << 1) + aCS) ^ (row & 7)) << 4);
                ldsm_x4(afr[mt], addr);
            }
            #pragma unroll
            for (int ntp = 0; ntp < 4; ntp++) {
                int row = bRowB + (ntp << 4);
                uint32_t addr = bsb + row * 128 + ((((ks << 1) + bCS) ^ (row & 7)) << 4);
                uint32_t b4[4];
                ldsm_x4(b4, addr);
                mma_fp16(acc[0][2 * ntp],     afr[0], b4);
                mma_fp16(acc[1][2 * ntp],     afr[1], b4);
                mma_fp16(acc[0][2 * ntp + 1], afr[0], b4 + 2);
                mma_fp16(acc[1][2 * ntp + 1], afr[1], b4 + 2);
            }
        }
    }

    #pragma unroll
    for (int mt = 0; mt < 2; mt++) {
        #pragma unroll
        for (int nt = 0; nt < 8; nt++) {
            int row = m0 + wm + (mt << 4) + lr;
            int col = n0 + wn + (nt << 3) + (lc << 1);
            *(float2*)&C[(size_t)row * N + col] =
                make_float2(acc[mt][nt][0], acc[mt][nt][1]);
            *(float2*)&C[(size_t)(row + 8) * N + col] =
                make_float2(acc[mt][nt][2], acc[mt][nt][3]);
        }
    }
}

// ---------------- vmean (single kernel, same summation order) ----------------
__global__ void vmean_all() {    // grid 8, block 1024
    __shared__ float part[8][HDN];
    int bn = blockIdx.x, tid = threadIdx.x;
    int d = tid & 127, ch = tid >> 7;
    int b = bn >> 2, n = bn & 3;
    float s = 0.f;
    int r0 = ch * 256;
    #pragma unroll 4
    for (int t = 0; t < 256; t++)
        s += g_qkv[(size_t)(b * SS + r0 + t) * NQKV + 2560 + n * HDN + d];
    part[ch][d] = s;
    __syncthreads();
    if (tid < HDN) {
        float a = 0.f;
        #pragma unroll
        for (int c = 0; c < 8; c++) a += part[c][tid];
        g_vmean[bn * HDN + tid] = a * (1.f / SS);
    }
}

// ---------------- compaction: scan + pad fused --------------------------------
__global__ void scan_pad_kernel() {
    __shared__ int wsum[32];
    int bn = blockIdx.x, t = threadIdx.x;
    int lane = t & 31, w = t >> 5;
    const float* bias = g_bias + bn * SS;
    int f0 = bias[2 * t]     > 0.f;
    int f1 = bias[2 * t + 1] > 0.f;
    int v = f0 + f1;
    int s = v;
    #pragma unroll
    for (int off = 1; off < 32; off <<= 1) {
        int u = __shfl_up_sync(0xffffffffu, s, off);
        if (lane >= off) s += u;
    }
    if (lane == 31) wsum[w] = s;
    __syncthreads();
    if (w == 0) {
        int ws = wsum[lane];
        #pragma unroll
        for (int off = 1; off < 32; off <<= 1) {
            int u = __shfl_up_sync(0xffffffffu, ws, off);
            if (lane >= off) ws += u;
        }
        wsum[lane] = ws;
    }
    __syncthreads();
    int base = (w > 0 ? wsum[w - 1] : 0) + s - v;
    int* pf = g_prefix + bn * (SS + 1);
    if (t == 0) pf[0] = 0;
    pf[2 * t + 1] = base + f0;
    pf[2 * t + 2] = base + f0 + f1;

    // pad 32 rows starting at total count (disjoint from gather's writes)
    int nc = wsum[31];
    int pos = nc + w;                      // w = 0..31 (32 warps)
    __half2 z = __floats2half2_rn(0.f, 0.f);
    __half* kdst = g_ckh + ((size_t)bn * CAP + pos) * HDN + lane * 4;
    __half* vdst = g_cvh + ((size_t)bn * CAP + pos) * HDN + lane * 4;
    *(__half2*)(kdst) = z; *(__half2*)(kdst + 2) = z;
    *(__half2*)(vdst) = z; *(__half2*)(vdst + 2) = z;
    if (lane == 0) { g_cidx[bn * CAP + pos] = 0x7fffffff; g_cb[bn * CAP + pos] = 0.f; }
}

__global__ void gather_kernel() {
    int bn = blockIdx.y;
    int b = bn >> 2, n = bn & 3;
    int w = threadIdx.x >> 5, lane = threadIdx.x & 31;
    int key = blockIdx.x * 8 + w;
    float bk = g_bias[bn * SS + key];
    if (bk > 0.f) {
        int pos = g_prefix[bn * (SS + 1) + key];
        size_t src = (size_t)(b * SS + key) * NQKV + 2048 + n * HDN + lane * 4;
        float4 kv = *(const float4*)(g_qkv + src);
        float4 vv = *(const float4*)(g_qkv + src + 512);
        int w0 = 2 * lane, w1 = w0 + 1;
        int p0 = (w0 & 56) | kperm8(w0 & 7);
        int p1 = (w1 & 56) | kperm8(w1 & 7);
        __half* kdst = g_ckh + ((size_t)bn * CAP + pos) * HDN;
        *(__half2*)(kdst + p0 * 2) = __floats2half2_rn(kv.x, kv.y);
        *(__half2*)(kdst + p1 * 2) = __floats2half2_rn(kv.z, kv.w);
        __half* vdst = g_cvh + ((size_t)bn * CAP + pos) * HDN + lane * 4;
        *(__half2*)(vdst)     = __floats2half2_rn(vv.x, vv.y);
        *(__half2*)(vdst + 2) = __floats2half2_rn(vv.z, vv.w);
        if (lane == 0) { g_cb[bn * CAP + pos] = bk; g_cidx[bn * CAP + pos] = key; }
    }
}

// ---------------- vtrans: V^T [bn][d][key] fp16, key pair-permuted ----------
__global__ void vtrans_kernel() {
    __shared__ float t[32][33];
    int k0 = blockIdx.x * 32, d0 = blockIdx.y * 32, bn = blockIdx.z;
    int tx = threadIdx.x & 31, ty = threadIdx.x >> 5;
    #pragma unroll
    for (int i = 0; i < 32; i += 8)
        t[ty + i][tx] = __half2float(g_cvh[((size_t)bn * CAP + k0 + ty + i) * HDN + d0 + tx]);
    __syncthreads();
    int kp = kph(tx);
    #pragma unroll
    for (int i = 0; i < 32; i += 8)
        g_cvth[((size_t)bn * HDN + d0 + ty + i) * CAP + k0 + kp] =
            __float2half_rn(t[tx][ty + i]);
}

// ---------------- fp16 tensor-core flash attention ---------------------------
#define QB   128
#define KB   32
#define Q_SH   (256*64)
#define K_SH   (64*64)
#define VT_SH  (128*48)
#define P_SH   (16*48)
#define ATTN_SMEM ((Q_SH + 2*K_SH + 2*VT_SH + 8*P_SH)*2 + 512)

__global__ __launch_bounds__(256) void attn_mma() {
    extern __shared__ __half sha[];
    __half* q_sh  = sha;
    __half* k_sh  = q_sh + Q_SH;
    __half* vt_sh = k_sh + 2 * K_SH;
    __half* p_sh  = vt_sh + 2 * VT_SH;
    float*  cb_sh = (float*)(p_sh + 8 * P_SH);
    int*    idx_sh = (int*)(cb_sh + 64);

    const int qblk = (gridDim.x - 1) - blockIdx.x;
    const int h    = blockIdx.y;
    const int b    = blockIdx.z;
    const int n    = h >> 2;
    const int bn   = b * HKVN + n;
    const int q0   = qblk * QB;
    const int tid  = threadIdx.x;
    const int w    = tid >> 5;
    const int lane = tid & 31;
    const int lr   = lane >> 2;
    const int lc   = lane & 3;
    const float scale = 0.08838834764831843f;

    {
        int qrow = tid >> 1;
        int sub  = tid & 1;
        int rr   = (qrow << 1) | sub;
        const float* src = g_qkv + (size_t)(b * SS + q0 + qrow) * NQKV + h * HDN + (sub << 6);
        __half* dst = q_sh + rr * 64;
        int xw = (rr & 3) << 3;
        #pragma unroll
        for (int j = 0; j < 16; j++) {
            float4 v = *(const float4*)(src + j * 4);
            int w0 = 2 * j, w1 = w0 + 1;
            int pp0 = (((w0 & 24) | kperm8(w0 & 7)) ^ xw);
            int pp1 = (((w1 & 24) | kperm8(w1 & 7)) ^ xw);
            *(__half2*)(dst + pp0 * 2) = __floats2half2_rn(v.x * scale, v.y * scale);
            *(__half2*)(dst + pp1 * 2) = __floats2half2_rn(v.z * scale, v.w * scale);
        }
    }

    const int limit  = g_prefix[bn * (SS + 1) + q0 + QB];
    const int ntiles = (limit + KB - 1) / KB;

    auto load_tile = [&](int kt, int st) {
        __half* ks = k_sh + st * K_SH;
        __half* vs = vt_sh + st * VT_SH;
        const __half* kg = g_ckh + ((size_t)bn * CAP + kt * KB) * HDN;
        #pragma unroll
        for (int p = 0; p < 2; p++) {
            int id = tid + (p << 8);
            int r = id >> 3, c = id & 7;
            uint32_t slot = (uint32_t)((2 * c) ^ ((r & 3) << 2));
            CP16((uint32_t)__cvta_generic_to_shared(ks + r * 64 + slot * 4),
                 kg + (size_t)(r >> 1) * HDN + ((r & 1) << 6) + c * 8);
        }
        #pragma unroll
        for (int p = 0; p < 2; p++) {
            int id = tid + (p << 8);
            int r = id >> 2, c = id & 3;
            CP16((uint32_t)__cvta_generic_to_shared(vs + r * 48 + c * 8),
                 g_cvth + ((size_t)bn * HDN + r) * CAP + kt * KB + c * 8);
        }
        if (tid < 8)
            CP16((uint32_t)__cvta_generic_to_shared(cb_sh + st * 32 + tid * 4),
                 g_cb + bn * CAP + kt * KB + tid * 4);
        else if (tid < 16)
            CP16((uint32_t)__cvta_generic_to_shared(idx_sh + st * 32 + (tid - 8) * 4),
                 g_cidx + bn * CAP + kt * KB + (tid - 8) * 4);
        asm volatile("cp.async.commit_group;");
    };

    float m0 = -INFINITY, m1 = -INFINITY, l0 = 0.f, l1 = 0.f;
    float oacc[16][4];
    #pragma unroll
    for (int nt = 0; nt < 16; nt++)
        #pragma unroll
        for (int i = 0; i < 4; i++) oacc[nt][i] = 0.f;

    const int qA = q0 + w * 16 + lr;
    __half* pw = p_sh + w * P_SH;

    if (ntiles > 0) load_tile(0, 0);

    for (int kt = 0; kt < ntiles; kt++) {
        const int st = kt & 1;
        asm volatile("cp.async.wait_group 0;");
        __syncthreads();
        if (kt + 1 < ntiles) load_tile(kt + 1, st ^ 1);

        const __half* ks = k_sh + st * K_SH;
        const __half* vs = vt_sh + st * VT_SH;
        const float*  cb = cb_sh + st * 32;
        const int*    ix = idx_sh + st * 32;

        float sc[4][4];
        #pragma unroll
        for (int nt = 0; nt < 4; nt++)
            #pragma unroll
            for (int i = 0; i < 4; i++) sc[nt][i] = 0.f;

        #pragma unroll
        for (int kc = 0; kc < 8; kc++) {
            const int dhi = kc >> 2, ksx = kc & 3;
            const int t3 = (2 * lr + dhi) & 3;
            const int fo = (4 * (ksx ^ t3) + lc) * 4;
            const int rr0 = (w << 5) + 2 * lr + dhi;
            uint2 f0 = *(const uint2*)(q_sh + rr0 * 64 + fo);
            uint2 f1 = *(const uint2*)(q_sh + (rr0 + 16) * 64 + fo);
            uint32_t a[4] = { f0.x, f1.x, f0.y, f1.y };
            #pragma unroll
            for (int nt = 0; nt < 4; nt++) {
                int kr = (nt << 4) + 2 * lr + dhi;
                uint2 g = *(const uint2*)(ks + kr * 64 + fo);
                uint32_t bb[2] = { g.x, g.y };
                mma_fp16(sc[nt], a, bb);
            }
        }

        #pragma unroll
        for (int nt = 0; nt < 4; nt++) {
            int c0 = nt * 8 + 2 * lc, c1 = c0 + 1;
            float bk0 = cb[c0], bk1 = cb[c1];
            int   i0  = ix[c0], i1  = ix[c1];
            sc[nt][0] = (i0 <= qA)     ? sc[nt][0] + bk0 : -INFINITY;
            sc[nt][1] = (i1 <= qA)     ? sc[nt][1] + bk1 : -INFINITY;
            sc[nt][2] = (i0 <= qA + 8) ? sc[nt][2] + bk0 : -INFINITY;
            sc[nt][3] = (i1 <= qA + 8) ? sc[nt][3] + bk1 : -INFINITY;
        }

        float tm0 = -INFINITY, tm1 = -INFINITY;
        #pragma unroll
        for (int nt = 0; nt < 4; nt++) {
            tm0 = fmaxf(tm0, fmaxf(sc[nt][0], sc[nt][1]));
            tm1 = fmaxf(tm1, fmaxf(sc[nt][2], sc[nt][3]));
        }
        tm0 = fmaxf(tm0, __shfl_xor_sync(0xffffffffu, tm0, 1));
        tm0 = fmaxf(tm0, __shfl_xor_sync(0xffffffffu, tm0, 2));
        tm1 = fmaxf(tm1, __shfl_xor_sync(0xffffffffu, tm1, 1));
        tm1 = fmaxf(tm1, __shfl_xor_sync(0xffffffffu, tm1, 2));
        float mn0 = fmaxf(m0, tm0), mn1 = fmaxf(m1, tm1);
        bool act0 = (mn0 > -INFINITY), act1 = (mn1 > -INFINITY);

        float rs0 = 0.f, rs1 = 0.f;
        #pragma unroll
        for (int nt = 0; nt < 4; nt++) {
            sc[nt][0] = act0 ? __expf(sc[nt][0] - mn0) : 0.f;
            sc[nt][1] = act0 ? __expf(sc[nt][1] - mn0) : 0.f;
            sc[nt][2] = act1 ? __expf(sc[nt][2] - mn1) : 0.f;
            sc[nt][3] = act1 ? __expf(sc[nt][3] - mn1) : 0.f;
            rs0 += sc[nt][0] + sc[nt][1];
            rs1 += sc[nt][2] + sc[nt][3];
        }
        rs0 += __shfl_xor_sync(0xffffffffu, rs0, 1);
        rs0 += __shfl_xor_sync(0xffffffffu, rs0, 2);
        rs1 += __shfl_xor_sync(0xffffffffu, rs1, 1);
        rs1 += __shfl_xor_sync(0xffffffffu, rs1, 2);

        float corr0 = (act0 && m0 > -INFINITY) ? __expf(m0 - mn0) : (act0 ? 0.f : 1.f);
        float corr1 = (act1 && m1 > -INFINITY) ? __expf(m1 - mn1) : (act1 ? 0.f : 1.f);
        l0 = l0 * corr0 + rs0;  m0 = mn0;
        l1 = l1 * corr1 + rs1;  m1 = mn1;
        #pragma unroll
        for (int nt = 0; nt < 16; nt++) {
            oacc[nt][0] *= corr0; oacc[nt][1] *= corr0;
            oacc[nt][2] *= corr1; oacc[nt][3] *= corr1;
        }

        #pragma unroll
        for (int nt = 0; nt < 4; nt++) {
            int wn_ = nt * 4 + lc;
            int pos = ((wn_ & 8) | kperm8(wn_ & 7)) * 2;
            *(__half2*)(pw + lr * 48 + pos)       = __floats2half2_rn(sc[nt][0], sc[nt][1]);
            *(__half2*)(pw + (lr + 8) * 48 + pos) = __floats2half2_rn(sc[nt][2], sc[nt][3]);
        }
        __syncwarp();

        #pragma unroll
        for (int kc = 0; kc < 2; kc++) {
            const int fo = kc * 16 + 4 * lc;
            uint2 p0 = *(const uint2*)(pw + lr * 48 + fo);
            uint2 p1 = *(const uint2*)(pw + (lr + 8) * 48 + fo);
            uint32_t a[4] = { p0.x, p1.x, p0.y, p1.y };
            #pragma unroll
            for (int nt = 0; nt < 16; nt++) {
                uint2 g = *(const uint2*)(vs + (nt * 8 + lr) * 48 + fo);
                uint32_t bb[2] = { g.x, g.y };
                mma_fp16(oacc[nt], a, bb);
            }
        }
        __syncwarp();
    }

    float inv0 = (l0 > 0.f) ? 1.f / l0 : 0.f;
    float inv1 = (l1 > 0.f) ? 1.f / l1 : 0.f;
    size_t row0 = (size_t)(b * SS + qA) * DD + h * HDN;
    size_t row1 = row0 + (size_t)8 * DD;
    #pragma unroll
    for (int nt = 0; nt < 16; nt++) {
        int corig = nt * 8 + 2 * lc;
        float2 r0, r1;
        if (l0 > 0.f) r0 = make_float2(oacc[nt][0] * inv0, oacc[nt][1] * inv0);
        else          r0 = make_float2(g_vmean[bn * HDN + corig], g_vmean[bn * HDN + corig + 1]);
        if (l1 > 0.f) r1 = make_float2(oacc[nt][2] * inv1, oacc[nt][3] * inv1);
        else          r1 = make_float2(g_vmean[bn * HDN + corig], g_vmean[bn * HDN + corig + 1]);
        *(__half2*)&g_oh[row0 + corig] = __floats2half2_rn(r0.x, r0.y);
        *(__half2*)&g_oh[row1 + corig] = __floats2half2_rn(r1.x, r1.y);
    }
}

// ---------------- launch -----------------------------------------------------
extern "C" void kernel_launch(void* const* d_in, const int* in_sizes, int n_in,
                              void* d_out, int out_size) {
    const float* X  = (const float*)d_in[0];
    const float* Wq = (const float*)d_in[1];
    const float* Wk = (const float*)d_in[2];
    const float* Wv = (const float*)d_in[3];
    const float* Wg = (const float*)d_in[4];
    const float* Wd = (const float*)d_in[5];
    const float* Wo = (const float*)d_in[6];
    float* out = (float*)d_out;

    float *qkvp;
    __half *xh, *wbTh, *woTh, *oh;
    cudaGetSymbolAddress((void**)&qkvp, g_qkv);
    cudaGetSymbolAddress((void**)&xh,   g_xh);
    cudaGetSymbolAddress((void**)&wbTh, g_wbTh);
    cudaGetSymbolAddress((void**)&woTh, g_woTh);
    cudaGetSymbolAddress((void**)&oh,   g_oh);

    cudaFuncSetAttribute(gemm_fp16, cudaFuncAttributeMaxDynamicSharedMemorySize, GEMM_SMEM);
    cudaFuncSetAttribute(attn_mma, cudaFuncAttributeMaxDynamicSharedMemorySize, ATTN_SMEM);

    fuse_both<<<512, 256>>>(Wq, Wg, Wv, Wd);                                 // 0
    transpose_all<<<dim3(160, DD / 32), 256>>>(Wq, Wk, Wv, Wo);              // 1
    prep_x3<<<MROWS / PXR, 256>>>(X);                                        // 2
    gemm_fp16<<<dim3(NQKV / 128, MROWS / 128), 256, GEMM_SMEM>>>(            // 3 (ncu -s 5)
        xh, wbTh, qkvp, MROWS, NQKV, DD);

    vmean_all<<<BB * HKVN, 1024>>>();
    scan_pad_kernel<<<BB * HKVN, 1024>>>();
    gather_kernel<<<dim3(SS / 8, BB * HKVN), 256>>>();
    vtrans_kernel<<<dim3(CAP / 32, HDN / 32, BB * HKVN), 256>>>();

    attn_mma<<<dim3(SS / QB, HH, BB), 256, ATTN_SMEM>>>();

    gemm_fp16<<<dim3(DD / 128, MROWS / 128), 256, GEMM_SMEM>>>(oh, woTh, out, MROWS, DD, DD);
}